// round 10
// baseline (speedup 1.0000x reference)
#include <cuda_runtime.h>
#include <math.h>

#define NRAYS 16384
#define MAXS 128

typedef unsigned long long u64;

// ---------------- scratch (device globals; no allocation allowed) ----------
__device__ float g_dirs[NRAYS * 3];
__device__ float g_dbuf[2][NRAYS * MAXS];
__device__ float g_sbuf[2][NRAYS * MAXS];
__device__ float g_dfine[NRAYS * 16];
__device__ float g_sdff[NRAYS * 16];

// ---------------- math helpers ---------------------------------------------
__device__ __forceinline__ float softplus_fast(float x) {
    float t = __expf(-fabsf(x));
    return fmaxf(x, 0.0f) + __logf(1.0f + t);
}
__device__ __forceinline__ float sigmoid_fast(float x) {
    return __fdividef(1.0f, 1.0f + __expf(-x));
}
__device__ __forceinline__ float sigmoid_precise(float x) {
    return 1.0f / (1.0f + expf(-x));
}

// ---------------- packed f32x2 helpers (Blackwell FFMA2) --------------------
__device__ __forceinline__ u64 pack2(float lo, float hi) {
    u64 r;
    asm("mov.b64 %0, {%1, %2};" : "=l"(r) : "f"(lo), "f"(hi));
    return r;
}
__device__ __forceinline__ void unpack2(u64 v, float& lo, float& hi) {
    asm("mov.b64 {%0, %1}, %2;" : "=f"(lo), "=f"(hi) : "l"(v));
}
__device__ __forceinline__ u64 ffma2(u64 a, u64 b, u64 c) {
    u64 d;
    asm("fma.rn.f32x2 %0, %1, %2, %3;" : "=l"(d) : "l"(a), "l"(b), "l"(c));
    return d;
}

// ---------------- init: normalize dirs, fill coarse d ----------------------
__global__ void init_kernel(const float* __restrict__ rd,
                            const float* __restrict__ nearp,
                            const float* __restrict__ farp) {
    int r = blockIdx.x * blockDim.x + threadIdx.x;
    if (r >= NRAYS) return;
    float dx = rd[r * 3 + 0], dy = rd[r * 3 + 1], dz = rd[r * 3 + 2];
    float nrm = sqrtf(dx * dx + dy * dy + dz * dz);
    dx /= nrm; dy /= nrm; dz /= nrm;
    g_dirs[r * 3 + 0] = dx; g_dirs[r * 3 + 1] = dy; g_dirs[r * 3 + 2] = dz;
    float nr = nearp[r], fr = farp[r];
    for (int j = 0; j < 64; j++) {
        float t = (float)j / 63.0f;
        g_dbuf[0][r * MAXS + j] = nr * (1.0f - t) + fr * t;
    }
}

// ---------------- SDF MLP: block-GEMM, 128 points per CTA, 128 threads ------
// thread tile: 4 pts x 16 q. warp = one q-group of 16 (uniform weight reads).
// smem layout (floats):
//   [0,4096)       w2s  [k][q]
//   [4096,12288)   hsh  [k][pt]  pt=128
//   [12288,12800)  partial [qg=4][pt=128]
//   [12800,12992)  w1s
//   [12992,13056)  b1s
//   [13056,13120)  b2s
//   [13120,13184)  w3s
//   [13184,13312)  pnorm
//   [13312]        b3s
#define SDF_SMEM_FLOATS 13320
__global__ void __launch_bounds__(128)
sdf_kernel(const float* __restrict__ o,
           const float* __restrict__ w1, const float* __restrict__ b1,
           const float* __restrict__ w2, const float* __restrict__ b2,
           const float* __restrict__ w3, const float* __restrict__ b3,
           int mode) {
    extern __shared__ __align__(16) float sm[];
    float* w2s    = sm;
    float* hsh    = sm + 4096;
    float* partial= sm + 12288;
    float* w1s    = sm + 12800;
    float* b1s    = sm + 12992;
    float* b2s    = sm + 13056;
    float* w3s    = sm + 13120;
    float* pnorm  = sm + 13184;
    float* b3s    = sm + 13312;

    int tid = threadIdx.x;
    for (int i = tid; i < 4096; i += 128) w2s[i] = w2[i];
    for (int i = tid; i < 192; i += 128) w1s[i] = w1[i];
    if (tid < 64) { b1s[tid] = b1[tid]; b2s[tid] = b2[tid]; w3s[tid] = w3[tid]; }
    if (tid == 0) b3s[0] = b3[0];
    __syncthreads();

    const float* dvals = mode ? g_dfine : g_dbuf[0];
    float* outp        = mode ? g_sdff  : g_sbuf[0];
    int spr    = mode ? 16 : 64;
    int stride = mode ? 16 : MAXS;

    // ---- layer 1: 128 threads = 128 pts, each does all 64 k (uniform w) ----
    {
        int pt = tid;
        int gp = blockIdx.x * 128 + pt;
        int ray = gp / spr;
        int j   = gp - ray * spr;
        float dv = dvals[ray * stride + j];
        float ox = o[ray * 3 + 0], oy = o[ray * 3 + 1], oz = o[ray * 3 + 2];
        float dx = g_dirs[ray * 3 + 0], dy = g_dirs[ray * 3 + 1], dz = g_dirs[ray * 3 + 2];
        float px = fmaf(dv, dx, ox), py = fmaf(dv, dy, oy), pz = fmaf(dv, dz, oz);
        pnorm[pt] = sqrtf(fmaf(px, px, fmaf(py, py, pz * pz)));
#pragma unroll 8
        for (int k = 0; k < 64; k++) {
            float a = b1s[k];
            a = fmaf(px, w1s[k], a);
            a = fmaf(py, w1s[64 + k], a);
            a = fmaf(pz, w1s[128 + k], a);
            hsh[k * 128 + pt] = softplus_fast(a);
        }
    }
    __syncthreads();

    // ---- layer 2: 128 threads = 32 pt-quads x 4 q-groups of 16 ----
    {
        int pq = tid & 31;          // pts 4pq .. 4pq+3
        int qg = tid >> 5;          // q group (warp-uniform): q0 = qg*16
        int q0 = qg * 16;

        u64 acc[4][8];
#pragma unroll
        for (int i = 0; i < 4; i++)
#pragma unroll
            for (int j = 0; j < 8; j++) acc[i][j] = 0;

#pragma unroll 2
        for (int k = 0; k < 64; k++) {
            float4 h4 = *(const float4*)&hsh[k * 128 + 4 * pq];
            const ulonglong2* wr = (const ulonglong2*)&w2s[k * 64 + q0];
            ulonglong2 wv0 = wr[0];
            ulonglong2 wv1 = wr[1];
            ulonglong2 wv2 = wr[2];
            ulonglong2 wv3 = wr[3];
            u64 h0 = pack2(h4.x, h4.x);
            u64 h1 = pack2(h4.y, h4.y);
            u64 h2 = pack2(h4.z, h4.z);
            u64 h3 = pack2(h4.w, h4.w);
#define DO_PT(i, hh) \
            acc[i][0] = ffma2(hh, wv0.x, acc[i][0]); \
            acc[i][1] = ffma2(hh, wv0.y, acc[i][1]); \
            acc[i][2] = ffma2(hh, wv1.x, acc[i][2]); \
            acc[i][3] = ffma2(hh, wv1.y, acc[i][3]); \
            acc[i][4] = ffma2(hh, wv2.x, acc[i][4]); \
            acc[i][5] = ffma2(hh, wv2.y, acc[i][5]); \
            acc[i][6] = ffma2(hh, wv3.x, acc[i][6]); \
            acc[i][7] = ffma2(hh, wv3.y, acc[i][7]);
            DO_PT(0, h0)
            DO_PT(1, h1)
            DO_PT(2, h2)
            DO_PT(3, h3)
#undef DO_PT
        }

        // epilogue: softplus + layer3 partials over my 16 q's, 4 pts
        float p[4] = {0.f, 0.f, 0.f, 0.f};
#pragma unroll
        for (int j = 0; j < 8; j++) {
            int q = q0 + 2 * j;
            float bql = b2s[q], bqh = b2s[q + 1];
            float wql = w3s[q], wqh = w3s[q + 1];
#pragma unroll
            for (int i = 0; i < 4; i++) {
                float lo, hi;
                unpack2(acc[i][j], lo, hi);
                p[i] = fmaf(softplus_fast(lo + bql), wql, p[i]);
                p[i] = fmaf(softplus_fast(hi + bqh), wqh, p[i]);
            }
        }
        *(float4*)&partial[qg * 128 + 4 * pq] = make_float4(p[0], p[1], p[2], p[3]);
    }
    __syncthreads();

    // ---- final reduce + write: 128 threads, one per point ----
    {
        float s = partial[tid] + partial[128 + tid] +
                  partial[256 + tid] + partial[384 + tid];
        int gp = blockIdx.x * 128 + tid;
        int ray = gp / spr;
        int j   = gp - ray * spr;
        outp[ray * stride + j] = pnorm[tid] - 0.8f + 0.1f * (b3s[0] + s);
    }
}

// ---------------- upsample: one warp per ray --------------------------------
#define UP_PAD 116
__global__ void upsample_kernel(int n, float s_i, int pp) {
    int gwarp = (blockIdx.x * blockDim.x + threadIdx.x) >> 5;
    int lane  = threadIdx.x & 31;
    int wib   = (threadIdx.x >> 5);
    __shared__ float scdf[8 * UP_PAD];
    if (gwarp >= NRAYS) return;

    const float* d  = g_dbuf[pp] + gwarp * MAXS;
    const float* sd = g_sbuf[pp] + gwarp * MAXS;
    int m = n - 1;
    int base = lane * 4;

    float dj[5], sj[5];
#pragma unroll
    for (int i = 0; i < 5; i++) {
        int idx = base + i;
        bool v = idx < n;
        dj[i] = v ? d[idx] : 1.0f;
        sj[i] = v ? sd[idx] : 0.0f;
    }

    float raw[4];
#pragma unroll
    for (int i = 0; i < 4; i++)
        raw[i] = (sj[i + 1] - sj[i]) / (dj[i + 1] - dj[i] + 1e-5f);

    float prevr = __shfl_up_sync(0xffffffffu, raw[3], 1);
    if (lane == 0) prevr = 0.0f;

    float alpha[4];
#pragma unroll
    for (int i = 0; i < 4; i++) {
        float dvv = fminf(prevr, raw[i]);
        prevr = raw[i];
        dvv = fminf(fmaxf(dvv, -10.0f), 0.0f);
        float mid  = 0.5f * (sj[i] + sj[i + 1]);
        float dist = dj[i + 1] - dj[i];
        float pe = mid - dvv * dist * 0.5f;
        float ne = mid + dvv * dist * 0.5f;
        float pc = sigmoid_precise(pe * s_i);
        float nc = sigmoid_precise(ne * s_i);
        alpha[i] = (pc - nc + 1e-5f) / (pc + 1e-5f);
    }

    float Tloc[4], pl = 1.0f;
#pragma unroll
    for (int i = 0; i < 4; i++) {
        Tloc[i] = pl;
        float om = (base + i < m) ? (1.0f - alpha[i] + 1e-10f) : 1.0f;
        pl *= om;
    }
    float v = pl;
#pragma unroll
    for (int off = 1; off < 32; off <<= 1) {
        float t = __shfl_up_sync(0xffffffffu, v, off);
        if (lane >= off) v *= t;
    }
    float exp_ = __shfl_up_sync(0xffffffffu, v, 1);
    if (lane == 0) exp_ = 1.0f;

    float wp[4], sl = 0.0f, sloc[4];
#pragma unroll
    for (int i = 0; i < 4; i++) {
        float T = exp_ * Tloc[i];
        wp[i] = (base + i < m) ? fmaf(alpha[i], T, 1e-5f) : 0.0f;
        sl += wp[i];
        sloc[i] = sl;
    }
    float tot = sl;
#pragma unroll
    for (int off = 16; off > 0; off >>= 1)
        tot += __shfl_xor_sync(0xffffffffu, tot, off);
    float vs = sl;
#pragma unroll
    for (int off = 1; off < 32; off <<= 1) {
        float t = __shfl_up_sync(0xffffffffu, vs, off);
        if (lane >= off) vs += t;
    }
    float exs = __shfl_up_sync(0xffffffffu, vs, 1);
    if (lane == 0) exs = 0.0f;

    float inv = 1.0f / tot;
    float* cdf = scdf + wib * UP_PAD;
    if (lane == 0) cdf[0] = 0.0f;
#pragma unroll
    for (int i = 0; i < 4; i++) {
        int j = base + i;
        if (j < m) cdf[j + 1] = (exs + sloc[i]) * inv;
    }
    __syncwarp();

    if (lane < 16) {
        float u = (float)lane / 15.0f;
        int lo = 0, hi = n;
        while (lo < hi) {
            int mm = (lo + hi) >> 1;
            if (cdf[mm] <= u) lo = mm + 1; else hi = mm;
        }
        int below = lo - 1;
        if (below < 0) below = 0;
        if (below > n - 1) below = n - 1;
        int above = lo;
        if (above > n - 1) above = n - 1;
        float cb = cdf[below], ca = cdf[above];
        float bb = d[below],   ba = d[above];
        float den = ca - cb;
        if (den < 1e-5f) den = 1.0f;
        float t = (u - cb) / den;
        g_dfine[gwarp * 16 + lane] = bb + t * (ba - bb);
    }
}

// ---------------- parallel stable merge (rank & scatter), ping-pong ---------
__global__ void merge_kernel(int n, int pp) {
    int gwarp = (blockIdx.x * blockDim.x + threadIdx.x) >> 5;
    int lane  = threadIdx.x & 31;
    if (gwarp >= NRAYS) return;
    const float* d  = g_dbuf[pp] + gwarp * MAXS;
    const float* sd = g_sbuf[pp] + gwarp * MAXS;
    float* dd = g_dbuf[pp ^ 1] + gwarp * MAXS;
    float* ds = g_sbuf[pp ^ 1] + gwarp * MAXS;
    const float* fd = g_dfine + gwarp * 16;
    const float* fs = g_sdff  + gwarp * 16;

    if (lane < 16) {
        float v = fd[lane];
        int lo = 0, hi = n;                // count old <= v
        while (lo < hi) { int mm = (lo + hi) >> 1; if (d[mm] <= v) lo = mm + 1; else hi = mm; }
        dd[lo + lane] = v;
        ds[lo + lane] = fs[lane];
    }
    for (int a = lane; a < n; a += 32) {
        float v = d[a];
        int lo = 0, hi = 16;               // count new < v
        while (lo < hi) { int mm = (lo + hi) >> 1; if (fd[mm] < v) lo = mm + 1; else hi = mm; }
        dd[a + lo] = v;
        ds[a + lo] = sd[a];
    }
}

// ---------------- final render: compositing + radiance MLP ------------------
__global__ void render_kernel(const float* __restrict__ o,
                              const float* __restrict__ sp,
                              const float* __restrict__ w1, const float* __restrict__ b1,
                              const float* __restrict__ w2, const float* __restrict__ b2,
                              float* __restrict__ out) {
    int r = blockIdx.x;
    int tid = threadIdx.x;
    __shared__ float dsh[128], cdfsh[128], alphash[128], scan[128];
    __shared__ float w1s[384], b1s[64], w2s[192], b2s[3];
    __shared__ float red0[128], red1[128], red2[128];

    for (int i = tid; i < 384; i += 128) w1s[i] = w1[i];
    for (int i = tid; i < 192; i += 128) w2s[i] = w2[i];
    if (tid < 64) b1s[tid] = b1[tid];
    if (tid < 3)  b2s[tid] = b2[tid];

    float s = sp[0];
    float dv = g_dbuf[0][r * MAXS + tid];
    dsh[tid] = dv;
    cdfsh[tid] = sigmoid_precise(g_sbuf[0][r * MAXS + tid] * s);
    __syncthreads();

    float a = 0.0f;
    if (tid < 127)
        a = fmaxf((cdfsh[tid] - cdfsh[tid + 1]) / (cdfsh[tid] + 1e-10f), 0.0f);
    alphash[tid] = a;
    __syncthreads();
    scan[tid] = (tid == 0) ? 1.0f : (1.0f - alphash[tid - 1] + 1e-10f);
    __syncthreads();
#pragma unroll
    for (int off = 1; off < 128; off <<= 1) {
        float t = (tid >= off) ? scan[tid - off] : 1.0f;
        __syncthreads();
        scan[tid] *= t;
        __syncthreads();
    }

    float rr = 0.f, gg = 0.f, bb = 0.f;
    if (tid < 127) {
        float vw = alphash[tid] * scan[tid];
        float dm = 0.5f * (dsh[tid] + dsh[tid + 1]);
        float ox = o[r * 3 + 0], oy = o[r * 3 + 1], oz = o[r * 3 + 2];
        float dx = g_dirs[r * 3 + 0], dy = g_dirs[r * 3 + 1], dz = g_dirs[r * 3 + 2];
        float x0 = fmaf(dm, dx, ox), x1 = fmaf(dm, dy, oy), x2 = fmaf(dm, dz, oz);
        float a0 = b2s[0], a1 = b2s[1], a2 = b2s[2];
#pragma unroll 8
        for (int j = 0; j < 64; j++) {
            float h = b1s[j];
            h = fmaf(x0, w1s[j], h);
            h = fmaf(x1, w1s[64 + j], h);
            h = fmaf(x2, w1s[128 + j], h);
            h = fmaf(dx, w1s[192 + j], h);
            h = fmaf(dy, w1s[256 + j], h);
            h = fmaf(dz, w1s[320 + j], h);
            h = softplus_fast(h);
            a0 = fmaf(h, w2s[j * 3 + 0], a0);
            a1 = fmaf(h, w2s[j * 3 + 1], a1);
            a2 = fmaf(h, w2s[j * 3 + 2], a2);
        }
        rr = sigmoid_fast(a0) * vw;
        gg = sigmoid_fast(a1) * vw;
        bb = sigmoid_fast(a2) * vw;
    }
    red0[tid] = rr; red1[tid] = gg; red2[tid] = bb;
    __syncthreads();
    for (int off = 64; off > 0; off >>= 1) {
        if (tid < off) {
            red0[tid] += red0[tid + off];
            red1[tid] += red1[tid + off];
            red2[tid] += red2[tid + off];
        }
        __syncthreads();
    }
    if (tid < 3) {
        float v = (tid == 0) ? red0[0] : (tid == 1) ? red1[0] : red2[0];
        out[r * 3 + tid] = v;
    }
}

// ---------------- launch ----------------------------------------------------
extern "C" void kernel_launch(void* const* d_in, const int* in_sizes, int n_in,
                              void* d_out, int out_size) {
    const float* rays_o = (const float*)d_in[0];
    const float* rays_d = (const float*)d_in[1];
    const float* nearp  = (const float*)d_in[2];
    const float* farp   = (const float*)d_in[3];
    const float* s_ptr  = (const float*)d_in[4];
    const float* sw1 = (const float*)d_in[5];
    const float* sb1 = (const float*)d_in[6];
    const float* sw2 = (const float*)d_in[7];
    const float* sb2 = (const float*)d_in[8];
    const float* sw3 = (const float*)d_in[9];
    const float* sb3 = (const float*)d_in[10];
    const float* rw1 = (const float*)d_in[11];
    const float* rb1 = (const float*)d_in[12];
    const float* rw2 = (const float*)d_in[13];
    const float* rb2 = (const float*)d_in[14];
    float* out = (float*)d_out;

    const int sdf_smem = SDF_SMEM_FLOATS * 4;
    cudaFuncSetAttribute(sdf_kernel,
                         cudaFuncAttributeMaxDynamicSharedMemorySize, sdf_smem);

    init_kernel<<<(NRAYS + 255) / 256, 256>>>(rays_d, nearp, farp);

    int cta_coarse = NRAYS * 64 / 128;   // 128 pts per CTA, 128 threads
    sdf_kernel<<<cta_coarse, 128, sdf_smem>>>(
        rays_o, sw1, sb1, sw2, sb2, sw3, sb3, 0);

    int cta_fine = NRAYS * 16 / 128;
    int warps_grid = (NRAYS * 32 + 255) / 256;   // one warp per ray
    int pp = 0;
    for (int i = 0; i < 4; i++) {
        int n = 64 + 16 * i;
        float si = 64.0f * (float)(1 << i);
        upsample_kernel<<<warps_grid, 256>>>(n, si, pp);
        sdf_kernel<<<cta_fine, 128, sdf_smem>>>(
            rays_o, sw1, sb1, sw2, sb2, sw3, sb3, 1);
        merge_kernel<<<warps_grid, 256>>>(n, pp);
        pp ^= 1;
    }
    // after 4 flips pp == 0: final data in buffer 0
    render_kernel<<<NRAYS, 128>>>(rays_o, s_ptr, rw1, rb1, rw2, rb2, out);
}

// round 11
// speedup vs baseline: 1.1125x; 1.1125x over previous
#include <cuda_runtime.h>
#include <math.h>

#define NRAYS 16384
#define MAXS 128

typedef unsigned long long u64;

// ---------------- scratch (device globals; no allocation allowed) ----------
__device__ float g_dirs[NRAYS * 3];
__device__ float g_dbuf[2][NRAYS * MAXS];
__device__ float g_sbuf[2][NRAYS * MAXS];
__device__ float g_dfine[NRAYS * 16];
__device__ float g_sdff[NRAYS * 16];

// ---------------- math helpers ---------------------------------------------
__device__ __forceinline__ float softplus_fast(float x) {
    float t = __expf(-fabsf(x));
    return fmaxf(x, 0.0f) + __logf(1.0f + t);
}
__device__ __forceinline__ float sigmoid_fast(float x) {
    return __fdividef(1.0f, 1.0f + __expf(-x));
}
__device__ __forceinline__ float sigmoid_precise(float x) {
    return 1.0f / (1.0f + expf(-x));
}

// ---------------- packed f32x2 helpers (Blackwell FFMA2) --------------------
__device__ __forceinline__ u64 pack2(float lo, float hi) {
    u64 r;
    asm("mov.b64 %0, {%1, %2};" : "=l"(r) : "f"(lo), "f"(hi));
    return r;
}
__device__ __forceinline__ void unpack2(u64 v, float& lo, float& hi) {
    asm("mov.b64 {%0, %1}, %2;" : "=f"(lo), "=f"(hi) : "l"(v));
}
__device__ __forceinline__ u64 ffma2(u64 a, u64 b, u64 c) {
    u64 d;
    asm("fma.rn.f32x2 %0, %1, %2, %3;" : "=l"(d) : "l"(a), "l"(b), "l"(c));
    return d;
}

// ---------------- init: normalize dirs, fill coarse d ----------------------
__global__ void init_kernel(const float* __restrict__ rd,
                            const float* __restrict__ nearp,
                            const float* __restrict__ farp) {
    int r = blockIdx.x * blockDim.x + threadIdx.x;
    if (r >= NRAYS) return;
    float dx = rd[r * 3 + 0], dy = rd[r * 3 + 1], dz = rd[r * 3 + 2];
    float nrm = sqrtf(dx * dx + dy * dy + dz * dz);
    dx /= nrm; dy /= nrm; dz /= nrm;
    g_dirs[r * 3 + 0] = dx; g_dirs[r * 3 + 1] = dy; g_dirs[r * 3 + 2] = dz;
    float nr = nearp[r], fr = farp[r];
    for (int j = 0; j < 64; j++) {
        float t = (float)j / 63.0f;
        g_dbuf[0][r * MAXS + j] = nr * (1.0f - t) + fr * t;
    }
}

// ---------------- SDF MLP: block-GEMM, 128 points per CTA, 256 threads ------
// thread tile: 4 pts x 8 q (R9 mapping), reg-capped for 4 CTAs/SM.
// smem layout (floats):
//   [0,4096)       w2s  [k][q]
//   [4096,12288)   hsh  [k][pt]  pt=128
//   [12288,13312)  partial [qg=8][pt=128]
//   [13312,13504)  w1s
//   [13504,13568)  b1s
//   [13568,13632)  b2s
//   [13632,13696)  w3s
//   [13696,13824)  pnorm
//   [13824]        b3s
#define SDF_SMEM_FLOATS 13832
__global__ void __launch_bounds__(256, 4)
sdf_kernel(const float* __restrict__ o,
           const float* __restrict__ w1, const float* __restrict__ b1,
           const float* __restrict__ w2, const float* __restrict__ b2,
           const float* __restrict__ w3, const float* __restrict__ b3,
           int mode) {
    extern __shared__ __align__(16) float sm[];
    float* w2s    = sm;
    float* hsh    = sm + 4096;
    float* partial= sm + 12288;
    float* w1s    = sm + 13312;
    float* b1s    = sm + 13504;
    float* b2s    = sm + 13568;
    float* w3s    = sm + 13632;
    float* pnorm  = sm + 13696;
    float* b3s    = sm + 13824;

    int tid = threadIdx.x;
    for (int i = tid; i < 4096; i += 256) w2s[i] = w2[i];
    if (tid < 192) w1s[tid] = w1[tid];
    if (tid < 64) { b1s[tid] = b1[tid]; b2s[tid] = b2[tid]; w3s[tid] = w3[tid]; }
    if (tid == 0) b3s[0] = b3[0];
    __syncthreads();

    const float* dvals = mode ? g_dfine : g_dbuf[0];
    float* outp        = mode ? g_sdff  : g_sbuf[0];
    int spr    = mode ? 16 : 64;
    int stride = mode ? 16 : MAXS;

    // ---- layer 1: 256 threads = 128 pts x 2 k-groups of 32 ----
    {
        int pt = tid & 127, kg = tid >> 7;
        int gp = blockIdx.x * 128 + pt;
        int ray = gp / spr;
        int j   = gp - ray * spr;
        float dv = dvals[ray * stride + j];
        float ox = o[ray * 3 + 0], oy = o[ray * 3 + 1], oz = o[ray * 3 + 2];
        float dx = g_dirs[ray * 3 + 0], dy = g_dirs[ray * 3 + 1], dz = g_dirs[ray * 3 + 2];
        float px = fmaf(dv, dx, ox), py = fmaf(dv, dy, oy), pz = fmaf(dv, dz, oz);
        if (kg == 0)
            pnorm[pt] = sqrtf(fmaf(px, px, fmaf(py, py, pz * pz)));
        int k0 = kg * 32;
#pragma unroll
        for (int k = k0; k < k0 + 32; k++) {
            float a = b1s[k];
            a = fmaf(px, w1s[k], a);
            a = fmaf(py, w1s[64 + k], a);
            a = fmaf(pz, w1s[128 + k], a);
            hsh[k * 128 + pt] = softplus_fast(a);
        }
    }
    __syncthreads();

    // ---- layer 2: 256 threads = 32 pt-quads x 8 q-groups of 8 ----
    {
        int pq = tid & 31;          // pts 4pq .. 4pq+3
        int qg = tid >> 5;          // q group (warp-uniform): q0 = qg*8
        int q0 = qg * 8;

        u64 acc[4][4];
#pragma unroll
        for (int i = 0; i < 4; i++)
#pragma unroll
            for (int j = 0; j < 4; j++) acc[i][j] = 0;

#pragma unroll 4
        for (int k = 0; k < 64; k++) {
            float4 h4 = *(const float4*)&hsh[k * 128 + 4 * pq];
            const ulonglong2* wr = (const ulonglong2*)&w2s[k * 64 + q0];
            ulonglong2 wA = wr[0];   // q0..q3 (2 packed pairs)
            ulonglong2 wB = wr[1];   // q4..q7
            u64 h0 = pack2(h4.x, h4.x);
            u64 h1 = pack2(h4.y, h4.y);
            u64 h2 = pack2(h4.z, h4.z);
            u64 h3 = pack2(h4.w, h4.w);
            acc[0][0] = ffma2(h0, wA.x, acc[0][0]);
            acc[0][1] = ffma2(h0, wA.y, acc[0][1]);
            acc[0][2] = ffma2(h0, wB.x, acc[0][2]);
            acc[0][3] = ffma2(h0, wB.y, acc[0][3]);
            acc[1][0] = ffma2(h1, wA.x, acc[1][0]);
            acc[1][1] = ffma2(h1, wA.y, acc[1][1]);
            acc[1][2] = ffma2(h1, wB.x, acc[1][2]);
            acc[1][3] = ffma2(h1, wB.y, acc[1][3]);
            acc[2][0] = ffma2(h2, wA.x, acc[2][0]);
            acc[2][1] = ffma2(h2, wA.y, acc[2][1]);
            acc[2][2] = ffma2(h2, wB.x, acc[2][2]);
            acc[2][3] = ffma2(h2, wB.y, acc[2][3]);
            acc[3][0] = ffma2(h3, wA.x, acc[3][0]);
            acc[3][1] = ffma2(h3, wA.y, acc[3][1]);
            acc[3][2] = ffma2(h3, wB.x, acc[3][2]);
            acc[3][3] = ffma2(h3, wB.y, acc[3][3]);
        }

        // epilogue: softplus + layer3 partials over my 8 q's, 4 pts
        float p0 = 0.f, p1 = 0.f, p2 = 0.f, p3 = 0.f;
#pragma unroll
        for (int j = 0; j < 4; j++) {
            int q = q0 + 2 * j;
            float bql = b2s[q], bqh = b2s[q + 1];
            float wql = w3s[q], wqh = w3s[q + 1];
            float lo, hi;
            unpack2(acc[0][j], lo, hi);
            p0 = fmaf(softplus_fast(lo + bql), wql, p0);
            p0 = fmaf(softplus_fast(hi + bqh), wqh, p0);
            unpack2(acc[1][j], lo, hi);
            p1 = fmaf(softplus_fast(lo + bql), wql, p1);
            p1 = fmaf(softplus_fast(hi + bqh), wqh, p1);
            unpack2(acc[2][j], lo, hi);
            p2 = fmaf(softplus_fast(lo + bql), wql, p2);
            p2 = fmaf(softplus_fast(hi + bqh), wqh, p2);
            unpack2(acc[3][j], lo, hi);
            p3 = fmaf(softplus_fast(lo + bql), wql, p3);
            p3 = fmaf(softplus_fast(hi + bqh), wqh, p3);
        }
        *(float4*)&partial[qg * 128 + 4 * pq] = make_float4(p0, p1, p2, p3);
    }
    __syncthreads();

    // ---- final reduce + write: 128 threads, one per point ----
    if (tid < 128) {
        float s = 0.0f;
#pragma unroll
        for (int g = 0; g < 8; g++) s += partial[g * 128 + tid];
        int gp = blockIdx.x * 128 + tid;
        int ray = gp / spr;
        int j   = gp - ray * spr;
        outp[ray * stride + j] = pnorm[tid] - 0.8f + 0.1f * (b3s[0] + s);
    }
}

// ---------------- upsample: one warp per ray --------------------------------
#define UP_PAD 116
__global__ void upsample_kernel(int n, float s_i, int pp) {
    int gwarp = (blockIdx.x * blockDim.x + threadIdx.x) >> 5;
    int lane  = threadIdx.x & 31;
    int wib   = (threadIdx.x >> 5);
    __shared__ float scdf[8 * UP_PAD];
    if (gwarp >= NRAYS) return;

    const float* d  = g_dbuf[pp] + gwarp * MAXS;
    const float* sd = g_sbuf[pp] + gwarp * MAXS;
    int m = n - 1;
    int base = lane * 4;

    float dj[5], sj[5];
#pragma unroll
    for (int i = 0; i < 5; i++) {
        int idx = base + i;
        bool v = idx < n;
        dj[i] = v ? d[idx] : 1.0f;
        sj[i] = v ? sd[idx] : 0.0f;
    }

    float raw[4];
#pragma unroll
    for (int i = 0; i < 4; i++)
        raw[i] = (sj[i + 1] - sj[i]) / (dj[i + 1] - dj[i] + 1e-5f);

    float prevr = __shfl_up_sync(0xffffffffu, raw[3], 1);
    if (lane == 0) prevr = 0.0f;

    float alpha[4];
#pragma unroll
    for (int i = 0; i < 4; i++) {
        float dvv = fminf(prevr, raw[i]);
        prevr = raw[i];
        dvv = fminf(fmaxf(dvv, -10.0f), 0.0f);
        float mid  = 0.5f * (sj[i] + sj[i + 1]);
        float dist = dj[i + 1] - dj[i];
        float pe = mid - dvv * dist * 0.5f;
        float ne = mid + dvv * dist * 0.5f;
        float pc = sigmoid_precise(pe * s_i);
        float nc = sigmoid_precise(ne * s_i);
        alpha[i] = (pc - nc + 1e-5f) / (pc + 1e-5f);
    }

    float Tloc[4], pl = 1.0f;
#pragma unroll
    for (int i = 0; i < 4; i++) {
        Tloc[i] = pl;
        float om = (base + i < m) ? (1.0f - alpha[i] + 1e-10f) : 1.0f;
        pl *= om;
    }
    float v = pl;
#pragma unroll
    for (int off = 1; off < 32; off <<= 1) {
        float t = __shfl_up_sync(0xffffffffu, v, off);
        if (lane >= off) v *= t;
    }
    float exp_ = __shfl_up_sync(0xffffffffu, v, 1);
    if (lane == 0) exp_ = 1.0f;

    float wp[4], sl = 0.0f, sloc[4];
#pragma unroll
    for (int i = 0; i < 4; i++) {
        float T = exp_ * Tloc[i];
        wp[i] = (base + i < m) ? fmaf(alpha[i], T, 1e-5f) : 0.0f;
        sl += wp[i];
        sloc[i] = sl;
    }
    float tot = sl;
#pragma unroll
    for (int off = 16; off > 0; off >>= 1)
        tot += __shfl_xor_sync(0xffffffffu, tot, off);
    float vs = sl;
#pragma unroll
    for (int off = 1; off < 32; off <<= 1) {
        float t = __shfl_up_sync(0xffffffffu, vs, off);
        if (lane >= off) vs += t;
    }
    float exs = __shfl_up_sync(0xffffffffu, vs, 1);
    if (lane == 0) exs = 0.0f;

    float inv = 1.0f / tot;
    float* cdf = scdf + wib * UP_PAD;
    if (lane == 0) cdf[0] = 0.0f;
#pragma unroll
    for (int i = 0; i < 4; i++) {
        int j = base + i;
        if (j < m) cdf[j + 1] = (exs + sloc[i]) * inv;
    }
    __syncwarp();

    if (lane < 16) {
        float u = (float)lane / 15.0f;
        int lo = 0, hi = n;
        while (lo < hi) {
            int mm = (lo + hi) >> 1;
            if (cdf[mm] <= u) lo = mm + 1; else hi = mm;
        }
        int below = lo - 1;
        if (below < 0) below = 0;
        if (below > n - 1) below = n - 1;
        int above = lo;
        if (above > n - 1) above = n - 1;
        float cb = cdf[below], ca = cdf[above];
        float bb = d[below],   ba = d[above];
        float den = ca - cb;
        if (den < 1e-5f) den = 1.0f;
        float t = (u - cb) / den;
        g_dfine[gwarp * 16 + lane] = bb + t * (ba - bb);
    }
}

// ---------------- parallel stable merge (rank & scatter), ping-pong ---------
__global__ void merge_kernel(int n, int pp) {
    int gwarp = (blockIdx.x * blockDim.x + threadIdx.x) >> 5;
    int lane  = threadIdx.x & 31;
    if (gwarp >= NRAYS) return;
    const float* d  = g_dbuf[pp] + gwarp * MAXS;
    const float* sd = g_sbuf[pp] + gwarp * MAXS;
    float* dd = g_dbuf[pp ^ 1] + gwarp * MAXS;
    float* ds = g_sbuf[pp ^ 1] + gwarp * MAXS;
    const float* fd = g_dfine + gwarp * 16;
    const float* fs = g_sdff  + gwarp * 16;

    if (lane < 16) {
        float v = fd[lane];
        int lo = 0, hi = n;                // count old <= v
        while (lo < hi) { int mm = (lo + hi) >> 1; if (d[mm] <= v) lo = mm + 1; else hi = mm; }
        dd[lo + lane] = v;
        ds[lo + lane] = fs[lane];
    }
    for (int a = lane; a < n; a += 32) {
        float v = d[a];
        int lo = 0, hi = 16;               // count new < v
        while (lo < hi) { int mm = (lo + hi) >> 1; if (fd[mm] < v) lo = mm + 1; else hi = mm; }
        dd[a + lo] = v;
        ds[a + lo] = sd[a];
    }
}

// ---------------- final render: compositing + radiance MLP ------------------
__global__ void render_kernel(const float* __restrict__ o,
                              const float* __restrict__ sp,
                              const float* __restrict__ w1, const float* __restrict__ b1,
                              const float* __restrict__ w2, const float* __restrict__ b2,
                              float* __restrict__ out) {
    int r = blockIdx.x;
    int tid = threadIdx.x;
    __shared__ float dsh[128], cdfsh[128], alphash[128], scan[128];
    __shared__ float w1s[384], b1s[64], w2s[192], b2s[3];
    __shared__ float red0[128], red1[128], red2[128];

    for (int i = tid; i < 384; i += 128) w1s[i] = w1[i];
    for (int i = tid; i < 192; i += 128) w2s[i] = w2[i];
    if (tid < 64) b1s[tid] = b1[tid];
    if (tid < 3)  b2s[tid] = b2[tid];

    float s = sp[0];
    float dv = g_dbuf[0][r * MAXS + tid];
    dsh[tid] = dv;
    cdfsh[tid] = sigmoid_precise(g_sbuf[0][r * MAXS + tid] * s);
    __syncthreads();

    float a = 0.0f;
    if (tid < 127)
        a = fmaxf((cdfsh[tid] - cdfsh[tid + 1]) / (cdfsh[tid] + 1e-10f), 0.0f);
    alphash[tid] = a;
    __syncthreads();
    scan[tid] = (tid == 0) ? 1.0f : (1.0f - alphash[tid - 1] + 1e-10f);
    __syncthreads();
#pragma unroll
    for (int off = 1; off < 128; off <<= 1) {
        float t = (tid >= off) ? scan[tid - off] : 1.0f;
        __syncthreads();
        scan[tid] *= t;
        __syncthreads();
    }

    float rr = 0.f, gg = 0.f, bb = 0.f;
    if (tid < 127) {
        float vw = alphash[tid] * scan[tid];
        float dm = 0.5f * (dsh[tid] + dsh[tid + 1]);
        float ox = o[r * 3 + 0], oy = o[r * 3 + 1], oz = o[r * 3 + 2];
        float dx = g_dirs[r * 3 + 0], dy = g_dirs[r * 3 + 1], dz = g_dirs[r * 3 + 2];
        float x0 = fmaf(dm, dx, ox), x1 = fmaf(dm, dy, oy), x2 = fmaf(dm, dz, oz);
        float a0 = b2s[0], a1 = b2s[1], a2 = b2s[2];
#pragma unroll 8
        for (int j = 0; j < 64; j++) {
            float h = b1s[j];
            h = fmaf(x0, w1s[j], h);
            h = fmaf(x1, w1s[64 + j], h);
            h = fmaf(x2, w1s[128 + j], h);
            h = fmaf(dx, w1s[192 + j], h);
            h = fmaf(dy, w1s[256 + j], h);
            h = fmaf(dz, w1s[320 + j], h);
            h = softplus_fast(h);
            a0 = fmaf(h, w2s[j * 3 + 0], a0);
            a1 = fmaf(h, w2s[j * 3 + 1], a1);
            a2 = fmaf(h, w2s[j * 3 + 2], a2);
        }
        rr = sigmoid_fast(a0) * vw;
        gg = sigmoid_fast(a1) * vw;
        bb = sigmoid_fast(a2) * vw;
    }
    red0[tid] = rr; red1[tid] = gg; red2[tid] = bb;
    __syncthreads();
    for (int off = 64; off > 0; off >>= 1) {
        if (tid < off) {
            red0[tid] += red0[tid + off];
            red1[tid] += red1[tid + off];
            red2[tid] += red2[tid + off];
        }
        __syncthreads();
    }
    if (tid < 3) {
        float v = (tid == 0) ? red0[0] : (tid == 1) ? red1[0] : red2[0];
        out[r * 3 + tid] = v;
    }
}

// ---------------- launch ----------------------------------------------------
extern "C" void kernel_launch(void* const* d_in, const int* in_sizes, int n_in,
                              void* d_out, int out_size) {
    const float* rays_o = (const float*)d_in[0];
    const float* rays_d = (const float*)d_in[1];
    const float* nearp  = (const float*)d_in[2];
    const float* farp   = (const float*)d_in[3];
    const float* s_ptr  = (const float*)d_in[4];
    const float* sw1 = (const float*)d_in[5];
    const float* sb1 = (const float*)d_in[6];
    const float* sw2 = (const float*)d_in[7];
    const float* sb2 = (const float*)d_in[8];
    const float* sw3 = (const float*)d_in[9];
    const float* sb3 = (const float*)d_in[10];
    const float* rw1 = (const float*)d_in[11];
    const float* rb1 = (const float*)d_in[12];
    const float* rw2 = (const float*)d_in[13];
    const float* rb2 = (const float*)d_in[14];
    float* out = (float*)d_out;

    const int sdf_smem = SDF_SMEM_FLOATS * 4;
    cudaFuncSetAttribute(sdf_kernel,
                         cudaFuncAttributeMaxDynamicSharedMemorySize, sdf_smem);

    init_kernel<<<(NRAYS + 255) / 256, 256>>>(rays_d, nearp, farp);

    int cta_coarse = NRAYS * 64 / 128;   // 128 pts per CTA
    sdf_kernel<<<cta_coarse, 256, sdf_smem>>>(
        rays_o, sw1, sb1, sw2, sb2, sw3, sb3, 0);

    int cta_fine = NRAYS * 16 / 128;
    int warps_grid = (NRAYS * 32 + 255) / 256;   // one warp per ray
    int pp = 0;
    for (int i = 0; i < 4; i++) {
        int n = 64 + 16 * i;
        float si = 64.0f * (float)(1 << i);
        upsample_kernel<<<warps_grid, 256>>>(n, si, pp);
        sdf_kernel<<<cta_fine, 256, sdf_smem>>>(
            rays_o, sw1, sb1, sw2, sb2, sw3, sb3, 1);
        merge_kernel<<<warps_grid, 256>>>(n, pp);
        pp ^= 1;
    }
    // after 4 flips pp == 0: final data in buffer 0
    render_kernel<<<NRAYS, 128>>>(rays_o, s_ptr, rw1, rb1, rw2, rb2, out);
}